// round 15
// baseline (speedup 1.0000x reference)
#include <cuda_runtime.h>
#include <cstdint>

#define NN 20000

// ---------------- device scratch ----------------
__device__ float g_z1 [NN * 64];
__device__ float g_hd1[NN * 64];
__device__ float g_zc [NN * 64];
__device__ float g_u  [NN * 64];

// ---------------- helpers ----------------
__device__ __forceinline__ float warpSumAll(float v) {
#pragma unroll
    for (int o = 16; o > 0; o >>= 1) v += __shfl_xor_sync(0xffffffffu, v, o);
    return v;
}
__device__ __forceinline__ float warpMaxAll(float v) {
#pragma unroll
    for (int o = 16; o > 0; o >>= 1) v = fmaxf(v, __shfl_xor_sync(0xffffffffu, v, o));
    return v;
}
__device__ __forceinline__ float lrelu(float x) { return x > 0.f ? x : 0.01f * x; }
__device__ __forceinline__ float eluf(float x) {
    if (x > 0.f) return x;
    if (x > -0.25f)
        return x * (1.f + x * (0.5f + x * (0.16666667f + x * 0.041666667f)));
    return __expf(x) - 1.f;
}

union F2U { float2 f; unsigned long long u; };
__device__ __forceinline__ void fma2(float2& c, float2 a, float2 b) {
    F2U A, B, C; A.f = a; B.f = b; C.f = c;
    asm("fma.rn.f32x2 %0, %1, %2, %0;" : "+l"(C.u) : "l"(A.u), "l"(B.u));
    c = C.f;
}

__device__ __forceinline__ void cpasync16(uint32_t dst, const void* src) {
    asm volatile("cp.async.ca.shared.global [%0], [%1], 16;" :: "r"(dst), "l"(src));
}
__device__ __forceinline__ void cp_commit() {
    asm volatile("cp.async.commit_group;" ::: "memory");
}
template <int N>
__device__ __forceinline__ void cp_wait() {
    asm volatile("cp.async.wait_group %0;" :: "n"(N) : "memory");
}

// =====================================================================
// cp.async-pipelined N-split FFMA2 GEMM, deep-M thread tile.
// Tile: 96 nodes x 64 outs (half = blockIdx.y), K=128 in 8 chunks of 16.
// Block = 192 thr (12 warps); grid (209,2)=418, 3 blocks/SM -> one wave.
// Thread tile 8 rows x 4 cols: doubles FFMA2 per B crossbar phase vs R13.
// A cp.async: thread copies ADJACENT segments {aseg0, aseg0+1}
//   (t&1=0 -> k0..7, t&1=1 -> k8..15)  -- R14's +2-segment bug fixed.
// =====================================================================
static constexpr int MT     = 96;
static constexpr int NTHR   = 192;
static constexpr int BPITCH = 68;
static constexpr int APITCH = 20;                 // 16 k + 4 pad (floats)
static constexpr int BS_ELEMS = 128 * BPITCH;     // 8704
static constexpr int ASTG_ELEMS = MT * APITCH;    // 1920 per stage
static constexpr int GSMEM = (BS_ELEMS + 3 * ASTG_ELEMS) * 4;  // 57856 B

template <int DEC>
__device__ __forceinline__ const float* srcA(const float* __restrict__ Ain, int node, int kg) {
    if (DEC) return (kg < 64) ? (g_zc + node * 64 + kg) : (g_u + node * 64 + kg - 64);
    return Ain + node * 128 + kg;
}

template <int DEC>
__global__ __launch_bounds__(NTHR, 3)
void gemm_f32(const float* __restrict__ Ain, const float* __restrict__ W0,
              const float* __restrict__ W1, float* __restrict__ Oout) {
    extern __shared__ __align__(16) float smem[];
    float* Bs = smem;                            // [128][BPITCH]
    float* As = smem + BS_ELEMS;                 // 3 x [MT][APITCH]

    const int t = threadIdx.x;
    const int tx = t & 15, ty = t >> 4;          // ty in 0..11
    const int node0 = blockIdx.x * MT;
    const int half  = blockIdx.y;
    const int c0 = 4 * tx;

    // cp.async: two ADJACENT 16B segments per thread per chunk
    const int arow0 = t >> 1, aseg0 = (t & 1) * 2;       // segs {0,1} or {2,3}
    const int anode0 = min(node0 + arow0, NN - 1);
    const uint32_t adst0 = (uint32_t)__cvta_generic_to_shared(As)
                         + (arow0 * APITCH + aseg0 * 4) * 4;

    // ---- stage W half once ----
    for (int i = t; i < 64 * 128; i += NTHR) {
        const int n = i >> 7, k = i & 127;
        float v;
        if (DEC) v = (k < 64) ? W0[(half * 64 + n) * 64 + k]
                              : W1[(half * 64 + n) * 64 + k - 64];
        else     v = half ? W1[n * 128 + k] : W0[n * 128 + k];
        Bs[k * BPITCH + n] = v;
    }

    // ---- prologue: issue A chunks 0 and 1 ----
#pragma unroll
    for (int s = 0; s < 2; s++) {
        cpasync16(adst0 + s * ASTG_ELEMS * 4,      srcA<DEC>(Ain, anode0, s * 16 + aseg0 * 4));
        cpasync16(adst0 + s * ASTG_ELEMS * 4 + 16, srcA<DEC>(Ain, anode0, s * 16 + (aseg0 + 1) * 4));
        cp_commit();
    }

    float2 acc[8][2];
#pragma unroll
    for (int i = 0; i < 8; i++) { acc[i][0] = make_float2(0.f, 0.f); acc[i][1] = make_float2(0.f, 0.f); }

    int stage = 0;
#pragma unroll 1
    for (int ch = 0; ch < 8; ch++) {
        if (ch < 7) cp_wait<1>(); else cp_wait<0>();
        __syncthreads();

        if (ch + 2 < 8) {
            const int nst = (stage + 2 >= 3) ? (stage - 1) : (stage + 2);
            cpasync16(adst0 + nst * ASTG_ELEMS * 4,
                      srcA<DEC>(Ain, anode0, (ch + 2) * 16 + aseg0 * 4));
            cpasync16(adst0 + nst * ASTG_ELEMS * 4 + 16,
                      srcA<DEC>(Ain, anode0, (ch + 2) * 16 + (aseg0 + 1) * 4));
            cp_commit();
        }

        const float* Ast = As + stage * ASTG_ELEMS;
        const float* Bb  = Bs + ch * 16 * BPITCH;
#pragma unroll
        for (int k4 = 0; k4 < 16; k4 += 4) {
            float a[8][4];
#pragma unroll
            for (int i = 0; i < 8; i++)
                *(float4*)a[i] = *(const float4*)&Ast[(8 * ty + i) * APITCH + k4];
#pragma unroll
            for (int kk = 0; kk < 4; kk++) {
                const float4 bv = *(const float4*)&Bb[(k4 + kk) * BPITCH + c0];
                const float2 b0 = make_float2(bv.x, bv.y);
                const float2 b1 = make_float2(bv.z, bv.w);
#pragma unroll
                for (int i = 0; i < 8; i++) {
                    const float2 av = make_float2(a[i][kk], a[i][kk]);
                    fma2(acc[i][0], av, b0);
                    fma2(acc[i][1], av, b1);
                }
            }
        }
        stage = (stage == 2) ? 0 : stage + 1;
    }

    // ---- epilogue ----
#pragma unroll
    for (int i = 0; i < 8; i++) {
        const int node = node0 + 8 * ty + i;
        if (node >= NN) break;
        const float4 v = make_float4(acc[i][0].x, acc[i][0].y, acc[i][1].x, acc[i][1].y);
        if (DEC) {
            *(float4*)(Oout + node * 128 + half * 64 + c0) = v;
        } else {
            float* dst = half ? g_hd1 : g_z1;
            *(float4*)(dst + node * 64 + c0) = v;
        }
    }
}

// ---------------- encoder aggregation: 3 hops + hop-attention combine ----------------
__global__ __launch_bounds__(256) void enc_agg(const float* __restrict__ attE,
                                               const float* __restrict__ attC) {
    __shared__ __align__(16) float hdT[56][66];
    __shared__ float sT[56];
    __shared__ __align__(16) float wS[3][25][36];
    __shared__ float sAe[64], sAc[64];

    const int t = threadIdx.x, w = t >> 5, lane = t & 31;
    const int nodeBase = blockIdx.x * 32;
    const int nl0 = w * 4;

    if (t < 64) { sAe[t] = attE[t]; sAc[t] = attC[t]; }

    for (int r = w; r < 56; r += 8) {
        int g = nodeBase - 24 + r;
        if (g < 0) g += NN;
        ((float2*)hdT[r])[lane] = ((const float2*)(g_hd1 + g * 64))[lane];
    }
    __syncthreads();

    for (int r = w; r < 56; r += 8) {
        float2 hv = ((float2*)hdT[r])[lane];
        float p = warpSumAll(hv.x * sAe[2 * lane] + hv.y * sAe[2 * lane + 1]);
        if (lane == 0) sT[r] = p;
    }
    __syncthreads();

#pragma unroll
    for (int j = 0; j < 4; j++) {
        const int li = 24 + nl0 + j;
        const float s_i = sT[li];
        float el = (lane < 25) ? lrelu(sT[li - lane] - s_i) : -1e30f;
        const float m1 = warpMaxAll(lane < 9  ? el : -1e30f);
        const float m2 = warpMaxAll(lane < 17 ? el : -1e30f);
        const float m3 = warpMaxAll(el);
        const float ex1 = (lane < 9)  ? __expf(el - m1) : 0.f;
        const float ex2 = (lane < 17) ? __expf(el - m2) : 0.f;
        const float ex3 = (lane < 25) ? __expf(el - m3) : 0.f;
        const float r1 = 1.f / warpSumAll(ex1);
        const float r2 = 1.f / warpSumAll(ex2);
        const float r3 = 1.f / warpSumAll(ex3);
        if (lane < 25) {
            wS[0][lane][nl0 + j] = ex1 * r1;
            wS[1][lane][nl0 + j] = ex2 * r2;
            wS[2][lane][nl0 + j] = ex3 * r3;
        }
    }
    __syncwarp();

    float2 A[4][3];
#pragma unroll
    for (int j = 0; j < 4; j++)
#pragma unroll
        for (int hh = 0; hh < 3; hh++) A[j][hh] = make_float2(0.f, 0.f);

#pragma unroll
    for (int tt = 0; tt < 25; tt++) {
        const float4 w3 = *(const float4*)&wS[2][tt][nl0];
        float4 w2, w1;
        if (tt < 17) w2 = *(const float4*)&wS[1][tt][nl0];
        if (tt < 9)  w1 = *(const float4*)&wS[0][tt][nl0];
#pragma unroll
        for (int j = 0; j < 4; j++) {
            const float2 hv = ((float2*)hdT[24 + nl0 + j - tt])[lane];
            const float g3 = ((const float*)&w3)[j];
            A[j][2].x = fmaf(g3, hv.x, A[j][2].x);
            A[j][2].y = fmaf(g3, hv.y, A[j][2].y);
            if (tt < 17) {
                const float g2 = ((const float*)&w2)[j];
                A[j][1].x = fmaf(g2, hv.x, A[j][1].x);
                A[j][1].y = fmaf(g2, hv.y, A[j][1].y);
            }
            if (tt < 9) {
                const float g1 = ((const float*)&w1)[j];
                A[j][0].x = fmaf(g1, hv.x, A[j][0].x);
                A[j][0].y = fmaf(g1, hv.y, A[j][0].y);
            }
        }
    }

    const float ac0 = sAc[2 * lane], ac1 = sAc[2 * lane + 1];
#pragma unroll
    for (int j = 0; j < 4; j++) {
        const int li = 24 + nl0 + j;
        const int node = nodeBase + nl0 + j;
        const float2 hvi = ((float2*)hdT[li])[lane];
        const float2 zv  = ((const float2*)(g_z1 + node * 64))[lane];
        float2 Z1, Z2, Z3;
        Z1.x = eluf(zv.x + A[j][0].x - hvi.x); Z1.y = eluf(zv.y + A[j][0].y - hvi.y);
        Z2.x = eluf(zv.x + A[j][1].x - hvi.x); Z2.y = eluf(zv.y + A[j][1].y - hvi.y);
        Z3.x = eluf(zv.x + A[j][2].x - hvi.x); Z3.y = eluf(zv.y + A[j][2].y - hvi.y);

        const float c1 = warpSumAll(Z1.x * ac0 + Z1.y * ac1);
        const float c2 = warpSumAll(Z2.x * ac0 + Z2.y * ac1);
        const float c3 = warpSumAll(Z3.x * ac0 + Z3.y * ac1);
        const float l1 = lrelu(c1), l2 = lrelu(c2), l3 = lrelu(c3);
        const float mx = fmaxf(l1, fmaxf(l2, l3));
        const float e1 = __expf(l1 - mx), e2 = __expf(l2 - mx), e3 = __expf(l3 - mx);
        const float rd = 1.f / (e1 + e2 + e3);

        float2 o;
        o.x = (e1 * Z1.x + e2 * Z2.x + e3 * Z3.x) * rd;
        o.y = (e1 * Z1.y + e2 * Z2.y + e3 * Z3.y) * rd;
        ((float2*)(g_zc + node * 64))[lane] = o;
    }
}

// ---------------- decoder aggregation in 64-dim latent ----------------
__global__ __launch_bounds__(256) void dec_agg(const float* __restrict__ diffD,
                                               const float* __restrict__ attD) {
    __shared__ __align__(16) float zT[56][66];
    __shared__ float sT[56];
    __shared__ __align__(16) float wS[25][36];
    __shared__ float sv[64];

    const int t = threadIdx.x, w = t >> 5, lane = t & 31;
    const int nodeBase = blockIdx.x * 32;
    const int nl0 = w * 4;

    if (t < 64) {
        float a = 0.f;
#pragma unroll 4
        for (int od = 0; od < 128; od++) a = fmaf(diffD[od * 64 + t], attD[od], a);
        sv[t] = a;
    }

    for (int r = w; r < 56; r += 8) {
        int g = nodeBase - 24 + r;
        if (g < 0) g += NN;
        ((float2*)zT[r])[lane] = ((const float2*)(g_zc + g * 64))[lane];
    }
    __syncthreads();

    for (int r = w; r < 56; r += 8) {
        float2 zv = ((float2*)zT[r])[lane];
        float p = warpSumAll(zv.x * sv[2 * lane] + zv.y * sv[2 * lane + 1]);
        if (lane == 0) sT[r] = p;
    }
    __syncthreads();

#pragma unroll
    for (int j = 0; j < 4; j++) {
        const int li = 24 + nl0 + j;
        const float s_i = sT[li];
        float el = (lane < 25) ? lrelu(sT[li - lane] - s_i) : -1e30f;
        const float m = warpMaxAll(el);
        const float ex = (lane < 25) ? __expf(el - m) : 0.f;
        const float rd = 1.f / warpSumAll(ex);
        if (lane < 25) wS[lane][nl0 + j] = ex * rd;
    }
    __syncwarp();

    float2 A[4];
#pragma unroll
    for (int j = 0; j < 4; j++) A[j] = make_float2(0.f, 0.f);

#pragma unroll
    for (int tt = 0; tt < 25; tt++) {
        const float4 wv = *(const float4*)&wS[tt][nl0];
#pragma unroll
        for (int j = 0; j < 4; j++) {
            const float2 zv = ((float2*)zT[24 + nl0 + j - tt])[lane];
            const float g = ((const float*)&wv)[j];
            A[j].x = fmaf(g, zv.x, A[j].x);
            A[j].y = fmaf(g, zv.y, A[j].y);
        }
    }

#pragma unroll
    for (int j = 0; j < 4; j++) {
        const int node = nodeBase + nl0 + j;
        const float2 zvi = ((float2*)zT[24 + nl0 + j])[lane];
        float2 o;
        o.x = A[j].x - zvi.x;
        o.y = A[j].y - zvi.y;
        ((float2*)(g_u + node * 64))[lane] = o;
    }
}

// ---------------- launch ----------------
extern "C" void kernel_launch(void* const* d_in, const int* in_sizes, int n_in,
                              void* d_out, int out_size) {
    const float* h        = (const float*)d_in[0];
    const float* fc_enc   = (const float*)d_in[1];
    const float* diff_enc = (const float*)d_in[2];
    const float* att_enc  = (const float*)d_in[3];
    const float* fc_dec   = (const float*)d_in[4];
    const float* diff_dec = (const float*)d_in[5];
    const float* att_dec  = (const float*)d_in[6];
    const float* att_comb = (const float*)d_in[7];
    float* out = (float*)d_out;

    cudaFuncSetAttribute(gemm_f32<0>, cudaFuncAttributeMaxDynamicSharedMemorySize, GSMEM);
    cudaFuncSetAttribute(gemm_f32<1>, cudaFuncAttributeMaxDynamicSharedMemorySize, GSMEM);

    dim3 gemmGrid((NN + MT - 1) / MT, 2);   // (209, 2), one wave @3/SM

    gemm_f32<0><<<gemmGrid, NTHR, GSMEM>>>(h, fc_enc, diff_enc, nullptr);
    enc_agg<<<NN / 32, 256>>>(att_enc, att_comb);
    dec_agg<<<NN / 32, 256>>>(diff_dec, att_dec);
    gemm_f32<1><<<gemmGrid, NTHR, GSMEM>>>(nullptr, fc_dec, diff_dec, out);
}

// round 16
// speedup vs baseline: 1.1210x; 1.1210x over previous
#include <cuda_runtime.h>
#include <cstdint>

#define NN 20000

// ---------------- device scratch ----------------
__device__ float g_z1 [NN * 64];
__device__ float g_hd1[NN * 64];
__device__ float g_zc [NN * 64];
__device__ float g_u  [NN * 64];

// ---------------- helpers ----------------
__device__ __forceinline__ float warpSumAll(float v) {
#pragma unroll
    for (int o = 16; o > 0; o >>= 1) v += __shfl_xor_sync(0xffffffffu, v, o);
    return v;
}
__device__ __forceinline__ float lrelu(float x) { return x > 0.f ? x : 0.01f * x; }
__device__ __forceinline__ float eluf(float x) {
    if (x > 0.f) return x;
    if (x > -0.25f)
        return x * (1.f + x * (0.5f + x * (0.16666667f + x * 0.041666667f)));
    return __expf(x) - 1.f;
}

union F2U { float2 f; unsigned long long u; };
__device__ __forceinline__ void fma2(float2& c, float2 a, float2 b) {
    F2U A, B, C; A.f = a; B.f = b; C.f = c;
    asm("fma.rn.f32x2 %0, %1, %2, %0;" : "+l"(C.u) : "l"(A.u), "l"(B.u));
    c = C.f;
}

__device__ __forceinline__ void cpasync16(uint32_t dst, const void* src) {
    asm volatile("cp.async.ca.shared.global [%0], [%1], 16;" :: "r"(dst), "l"(src));
}
__device__ __forceinline__ void cp_commit() {
    asm volatile("cp.async.commit_group;" ::: "memory");
}
template <int N>
__device__ __forceinline__ void cp_wait() {
    asm volatile("cp.async.wait_group %0;" :: "n"(N) : "memory");
}

// =====================================================================
// GEMM: exact R13 config (best: 88.9us). 96x64 tile, 384 thr, (209,2),
// 3 blocks/SM one wave; W half resident; A cp.async 3-stage ring.
// =====================================================================
static constexpr int MT     = 96;
static constexpr int NTHR   = 384;
static constexpr int BPITCH = 68;
static constexpr int APITCH = 20;
static constexpr int BS_ELEMS = 128 * BPITCH;
static constexpr int ASTG_ELEMS = MT * APITCH;
static constexpr int GSMEM = (BS_ELEMS + 3 * ASTG_ELEMS) * 4;  // 57856 B

template <int DEC>
__device__ __forceinline__ const float* srcA(const float* __restrict__ Ain, int node, int kg) {
    if (DEC) return (kg < 64) ? (g_zc + node * 64 + kg) : (g_u + node * 64 + kg - 64);
    return Ain + node * 128 + kg;
}

template <int DEC>
__global__ __launch_bounds__(NTHR, 3)
void gemm_f32(const float* __restrict__ Ain, const float* __restrict__ W0,
              const float* __restrict__ W1, float* __restrict__ Oout) {
    extern __shared__ __align__(16) float smem[];
    float* Bs = smem;
    float* As = smem + BS_ELEMS;

    const int t = threadIdx.x;
    const int tx = t & 15, ty = t >> 4;
    const int node0 = blockIdx.x * MT;
    const int half  = blockIdx.y;
    const int c0 = 4 * tx;

    const int arow = t >> 2, aseg = t & 3;
    const int anode = min(node0 + arow, NN - 1);
    const uint32_t adst_base = (uint32_t)__cvta_generic_to_shared(As)
                             + (arow * APITCH + aseg * 4) * 4;

    for (int i = t; i < 64 * 128; i += NTHR) {
        const int n = i >> 7, k = i & 127;
        float v;
        if (DEC) v = (k < 64) ? W0[(half * 64 + n) * 64 + k]
                              : W1[(half * 64 + n) * 64 + k - 64];
        else     v = half ? W1[n * 128 + k] : W0[n * 128 + k];
        Bs[k * BPITCH + n] = v;
    }

    cpasync16(adst_base + 0 * ASTG_ELEMS * 4, srcA<DEC>(Ain, anode, 0 * 16 + aseg * 4));
    cp_commit();
    cpasync16(adst_base + 1 * ASTG_ELEMS * 4, srcA<DEC>(Ain, anode, 1 * 16 + aseg * 4));
    cp_commit();

    float2 acc[4][2];
#pragma unroll
    for (int i = 0; i < 4; i++) { acc[i][0] = make_float2(0.f, 0.f); acc[i][1] = make_float2(0.f, 0.f); }

    int stage = 0;
#pragma unroll 1
    for (int ch = 0; ch < 8; ch++) {
        if (ch < 7) cp_wait<1>(); else cp_wait<0>();
        __syncthreads();

        if (ch + 2 < 8) {
            const int nst = (stage + 2 >= 3) ? (stage - 1) : (stage + 2);
            cpasync16(adst_base + nst * ASTG_ELEMS * 4,
                      srcA<DEC>(Ain, anode, (ch + 2) * 16 + aseg * 4));
            cp_commit();
        }

        const float* Ast = As + stage * ASTG_ELEMS;
        const float* Bb  = Bs + ch * 16 * BPITCH;
#pragma unroll
        for (int k4 = 0; k4 < 16; k4 += 4) {
            float a[4][4];
#pragma unroll
            for (int i = 0; i < 4; i++)
                *(float4*)a[i] = *(const float4*)&Ast[(4 * ty + i) * APITCH + k4];
#pragma unroll
            for (int kk = 0; kk < 4; kk++) {
                const float4 bv = *(const float4*)&Bb[(k4 + kk) * BPITCH + c0];
                const float2 b0 = make_float2(bv.x, bv.y);
                const float2 b1 = make_float2(bv.z, bv.w);
#pragma unroll
                for (int i = 0; i < 4; i++) {
                    const float2 av = make_float2(a[i][kk], a[i][kk]);
                    fma2(acc[i][0], av, b0);
                    fma2(acc[i][1], av, b1);
                }
            }
        }
        stage = (stage == 2) ? 0 : stage + 1;
    }

#pragma unroll
    for (int i = 0; i < 4; i++) {
        const int node = node0 + 4 * ty + i;
        if (node >= NN) break;
        const float4 v = make_float4(acc[i][0].x, acc[i][0].y, acc[i][1].x, acc[i][1].y);
        if (DEC) {
            *(float4*)(Oout + node * 128 + half * 64 + c0) = v;
        } else {
            float* dst = half ? g_hd1 : g_z1;
            *(float4*)(dst + node * 64 + c0) = v;
        }
    }
}

// =====================================================================
// encoder aggregation: lane-parallel softmax (warp 0, 1 lane = 1 node).
// Softmax shift-invariance: one exp-set (hop-3 max) serves all 3 hops.
// =====================================================================
__global__ __launch_bounds__(256) void enc_agg(const float* __restrict__ attE,
                                               const float* __restrict__ attC) {
    __shared__ __align__(16) float hdT[56][66];
    __shared__ float sT[56];
    __shared__ __align__(16) float wS[3][25][36];
    __shared__ float sAe[64], sAc[64];

    const int t = threadIdx.x, w = t >> 5, lane = t & 31;
    const int nodeBase = blockIdx.x * 32;
    const int nl0 = w * 4;

    if (t < 64) { sAe[t] = attE[t]; sAc[t] = attC[t]; }

    for (int r = w; r < 56; r += 8) {
        int g = nodeBase - 24 + r;
        if (g < 0) g += NN;
        ((float2*)hdT[r])[lane] = ((const float2*)(g_hd1 + g * 64))[lane];
    }
    __syncthreads();

    for (int r = w; r < 56; r += 8) {
        float2 hv = ((float2*)hdT[r])[lane];
        float p = warpSumAll(hv.x * sAe[2 * lane] + hv.y * sAe[2 * lane + 1]);
        if (lane == 0) sT[r] = p;
    }
    __syncthreads();

    // ---- lane-parallel softmax weights: warp 0, lane = node ----
    if (t < 32) {
        const int li = 24 + t;
        const float s_i = sT[li];
        float e[25];
#pragma unroll
        for (int tt = 0; tt < 25; tt++) e[tt] = lrelu(sT[li - tt] - s_i);
        float m = e[0];
#pragma unroll
        for (int tt = 1; tt < 25; tt++) m = fmaxf(m, e[tt]);
#pragma unroll
        for (int tt = 0; tt < 25; tt++) e[tt] = __expf(e[tt] - m);
        float p1 = 0.f, p2 = 0.f, p3 = 0.f;
#pragma unroll
        for (int tt = 0; tt < 25; tt++) {
            if (tt < 9)  p1 += e[tt];
            if (tt < 17) p2 += e[tt];
            p3 += e[tt];
        }
        const float r1 = 1.f / p1, r2 = 1.f / p2, r3 = 1.f / p3;
#pragma unroll
        for (int tt = 0; tt < 25; tt++) {
            if (tt < 9)  wS[0][tt][t] = e[tt] * r1;
            if (tt < 17) wS[1][tt][t] = e[tt] * r2;
            wS[2][tt][t] = e[tt] * r3;
        }
    }
    __syncthreads();

    float2 A[4][3];
#pragma unroll
    for (int j = 0; j < 4; j++)
#pragma unroll
        for (int hh = 0; hh < 3; hh++) A[j][hh] = make_float2(0.f, 0.f);

#pragma unroll
    for (int tt = 0; tt < 25; tt++) {
        const float4 w3 = *(const float4*)&wS[2][tt][nl0];
        float4 w2, w1;
        if (tt < 17) w2 = *(const float4*)&wS[1][tt][nl0];
        if (tt < 9)  w1 = *(const float4*)&wS[0][tt][nl0];
#pragma unroll
        for (int j = 0; j < 4; j++) {
            const float2 hv = ((float2*)hdT[24 + nl0 + j - tt])[lane];
            const float g3 = ((const float*)&w3)[j];
            A[j][2].x = fmaf(g3, hv.x, A[j][2].x);
            A[j][2].y = fmaf(g3, hv.y, A[j][2].y);
            if (tt < 17) {
                const float g2 = ((const float*)&w2)[j];
                A[j][1].x = fmaf(g2, hv.x, A[j][1].x);
                A[j][1].y = fmaf(g2, hv.y, A[j][1].y);
            }
            if (tt < 9) {
                const float g1 = ((const float*)&w1)[j];
                A[j][0].x = fmaf(g1, hv.x, A[j][0].x);
                A[j][0].y = fmaf(g1, hv.y, A[j][0].y);
            }
        }
    }

    const float ac0 = sAc[2 * lane], ac1 = sAc[2 * lane + 1];
#pragma unroll
    for (int j = 0; j < 4; j++) {
        const int li = 24 + nl0 + j;
        const int node = nodeBase + nl0 + j;
        const float2 hvi = ((float2*)hdT[li])[lane];
        const float2 zv  = ((const float2*)(g_z1 + node * 64))[lane];
        float2 Z1, Z2, Z3;
        Z1.x = eluf(zv.x + A[j][0].x - hvi.x); Z1.y = eluf(zv.y + A[j][0].y - hvi.y);
        Z2.x = eluf(zv.x + A[j][1].x - hvi.x); Z2.y = eluf(zv.y + A[j][1].y - hvi.y);
        Z3.x = eluf(zv.x + A[j][2].x - hvi.x); Z3.y = eluf(zv.y + A[j][2].y - hvi.y);

        const float c1 = warpSumAll(Z1.x * ac0 + Z1.y * ac1);
        const float c2 = warpSumAll(Z2.x * ac0 + Z2.y * ac1);
        const float c3 = warpSumAll(Z3.x * ac0 + Z3.y * ac1);
        const float l1 = lrelu(c1), l2 = lrelu(c2), l3 = lrelu(c3);
        const float mx = fmaxf(l1, fmaxf(l2, l3));
        const float e1 = __expf(l1 - mx), e2 = __expf(l2 - mx), e3 = __expf(l3 - mx);
        const float rd = 1.f / (e1 + e2 + e3);

        float2 o;
        o.x = (e1 * Z1.x + e2 * Z2.x + e3 * Z3.x) * rd;
        o.y = (e1 * Z1.y + e2 * Z2.y + e3 * Z3.y) * rd;
        ((float2*)(g_zc + node * 64))[lane] = o;
    }
}

// =====================================================================
// decoder aggregation: lane-parallel softmax (single hop).
// =====================================================================
__global__ __launch_bounds__(256) void dec_agg(const float* __restrict__ diffD,
                                               const float* __restrict__ attD) {
    __shared__ __align__(16) float zT[56][66];
    __shared__ float sT[56];
    __shared__ __align__(16) float wS[25][36];
    __shared__ float sv[64];

    const int t = threadIdx.x, w = t >> 5, lane = t & 31;
    const int nodeBase = blockIdx.x * 32;
    const int nl0 = w * 4;

    if (t < 64) {
        float a = 0.f;
#pragma unroll 4
        for (int od = 0; od < 128; od++) a = fmaf(diffD[od * 64 + t], attD[od], a);
        sv[t] = a;
    }

    for (int r = w; r < 56; r += 8) {
        int g = nodeBase - 24 + r;
        if (g < 0) g += NN;
        ((float2*)zT[r])[lane] = ((const float2*)(g_zc + g * 64))[lane];
    }
    __syncthreads();

    for (int r = w; r < 56; r += 8) {
        float2 zv = ((float2*)zT[r])[lane];
        float p = warpSumAll(zv.x * sv[2 * lane] + zv.y * sv[2 * lane + 1]);
        if (lane == 0) sT[r] = p;
    }
    __syncthreads();

    if (t < 32) {
        const int li = 24 + t;
        const float s_i = sT[li];
        float e[25];
#pragma unroll
        for (int tt = 0; tt < 25; tt++) e[tt] = lrelu(sT[li - tt] - s_i);
        float m = e[0];
#pragma unroll
        for (int tt = 1; tt < 25; tt++) m = fmaxf(m, e[tt]);
        float p = 0.f;
#pragma unroll
        for (int tt = 0; tt < 25; tt++) { e[tt] = __expf(e[tt] - m); p += e[tt]; }
        const float rd = 1.f / p;
#pragma unroll
        for (int tt = 0; tt < 25; tt++) wS[tt][t] = e[tt] * rd;
    }
    __syncthreads();

    float2 A[4];
#pragma unroll
    for (int j = 0; j < 4; j++) A[j] = make_float2(0.f, 0.f);

#pragma unroll
    for (int tt = 0; tt < 25; tt++) {
        const float4 wv = *(const float4*)&wS[tt][nl0];
#pragma unroll
        for (int j = 0; j < 4; j++) {
            const float2 zv = ((float2*)zT[24 + nl0 + j - tt])[lane];
            const float g = ((const float*)&wv)[j];
            A[j].x = fmaf(g, zv.x, A[j].x);
            A[j].y = fmaf(g, zv.y, A[j].y);
        }
    }

#pragma unroll
    for (int j = 0; j < 4; j++) {
        const int node = nodeBase + nl0 + j;
        const float2 zvi = ((float2*)zT[24 + nl0 + j])[lane];
        float2 o;
        o.x = A[j].x - zvi.x;
        o.y = A[j].y - zvi.y;
        ((float2*)(g_u + node * 64))[lane] = o;
    }
}

// ---------------- launch ----------------
extern "C" void kernel_launch(void* const* d_in, const int* in_sizes, int n_in,
                              void* d_out, int out_size) {
    const float* h        = (const float*)d_in[0];
    const float* fc_enc   = (const float*)d_in[1];
    const float* diff_enc = (const float*)d_in[2];
    const float* att_enc  = (const float*)d_in[3];
    const float* fc_dec   = (const float*)d_in[4];
    const float* diff_dec = (const float*)d_in[5];
    const float* att_dec  = (const float*)d_in[6];
    const float* att_comb = (const float*)d_in[7];
    float* out = (float*)d_out;

    cudaFuncSetAttribute(gemm_f32<0>, cudaFuncAttributeMaxDynamicSharedMemorySize, GSMEM);
    cudaFuncSetAttribute(gemm_f32<1>, cudaFuncAttributeMaxDynamicSharedMemorySize, GSMEM);

    dim3 gemmGrid((NN + MT - 1) / MT, 2);   // (209, 2), one wave @3/SM

    gemm_f32<0><<<gemmGrid, NTHR, GSMEM>>>(h, fc_enc, diff_enc, nullptr);
    enc_agg<<<NN / 32, 256>>>(att_enc, att_comb);
    dec_agg<<<NN / 32, 256>>>(diff_dec, att_dec);
    gemm_f32<1><<<gemmGrid, NTHR, GSMEM>>>(nullptr, fc_dec, diff_dec, out);
}